// round 13
// baseline (speedup 1.0000x reference)
#include <cuda_runtime.h>
#include <cstdint>

#define MAXV 10000.0f

namespace {
constexpr int W = 1024;
constexpr int H = 1024;
constexpr int X4 = W / 4;         // 256 float4 columns
constexpr int STRIP = 8;          // output rows per thread
constexpr int NSTRIP = H / STRIP; // 128
}

__device__ __forceinline__ float4 f4const(float v) {
    return make_float4(v, v, v, v);
}

__device__ __forceinline__ float4 min3v(float4 a, float4 b, float4 c) {
    float4 o;
    o.x = fminf(fminf(a.x, b.x), c.x);
    o.y = fminf(fminf(a.y, b.y), c.y);
    o.z = fminf(fminf(a.z, b.z), c.z);
    o.w = fminf(fminf(a.w, b.w), c.w);
    return o;
}

// Horizontal min over {x-1, x, x+1}, no kernel bias (all taps active).
// The scalar halo loads hit 128B lines already fetched by neighboring lanes'
// float4 loads -> L1/L2 hits, no extra DRAM traffic.
__device__ __forceinline__ float4 hmin_fast(const float* __restrict__ row, int x4) {
    const float4 v = *reinterpret_cast<const float4*>(row + x4);
    const float l = (x4 == 0) ? MAXV : row[x4 - 1];
    const float r = (x4 == W - 4) ? MAXV : row[x4 + 4];
    float4 h;
    h.x = fminf(fminf(l,   v.x), v.y);
    h.y = fminf(fminf(v.x, v.y), v.z);
    h.z = fminf(fminf(v.y, v.z), v.w);
    h.w = fminf(fminf(v.z, v.w), r);
    return h;
}

// Horizontal min with per-tap bias (bias = +MAXV where kernel tap == 0).
__device__ __forceinline__ float4 hmin_bias(const float* __restrict__ row, int x4,
                                            float b0, float b1, float b2) {
    const float4 v = *reinterpret_cast<const float4*>(row + x4);
    const float l = (x4 == 0) ? MAXV : row[x4 - 1];
    const float r = (x4 == W - 4) ? MAXV : row[x4 + 4];
    float4 h;
    h.x = fminf(fminf(l   + b0, v.x + b1), v.y + b2);
    h.y = fminf(fminf(v.x + b0, v.y + b1), v.z + b2);
    h.z = fminf(fminf(v.y + b0, v.z + b1), v.w + b2);
    h.w = fminf(fminf(v.z + b0, v.w + b1), r   + b2);
    return h;
}

__global__ void __launch_bounds__(256)
erosion3x3_kernel(const float* __restrict__ in,
                  const float* __restrict__ kern,
                  float* __restrict__ out) {
    const int t = blockIdx.x * blockDim.x + threadIdx.x;
    const int x4    = (t & (X4 - 1)) << 2;          // 0..1020 (16B aligned)
    const int strip = (t >> 8) & (NSTRIP - 1);      // 0..127
    const int img   = t >> 15;                      // image index (B*C)

    const size_t base = (size_t)img * (size_t)(W * H);
    const float* __restrict__ p = in  + base;
    float*       __restrict__ q = out + base;
    const int y0 = strip * STRIP;

    // Read 3x3 structuring element; bias = +MAXV where tap == 0
    // (reference: term = padded - neigh, neigh = -MAXV for inactive taps).
    float kb[3][3];
    bool allActive = true;
    #pragma unroll
    for (int i = 0; i < 3; ++i)
        #pragma unroll
        for (int j = 0; j < 3; ++j) {
            const float kv = kern[i * 3 + j];
            const bool act = (kv != 0.0f);
            kb[i][j] = act ? 0.0f : MAXV;
            allActive &= act;
        }

    if (allActive) {
        // ---------- fast path: plain 3x3 min filter, rolling vertical min ----------
        float4 hp = (y0 == 0) ? f4const(MAXV) : hmin_fast(p + (size_t)(y0 - 1) * W, x4);
        float4 hc = hmin_fast(p + (size_t)y0 * W, x4);
        #pragma unroll
        for (int r = 0; r < STRIP; ++r) {
            const int y = y0 + r;
            const float4 hn = (y + 1 < H) ? hmin_fast(p + (size_t)(y + 1) * W, x4)
                                          : f4const(MAXV);
            __stcs(reinterpret_cast<float4*>(q + (size_t)y * W + x4), min3v(hp, hc, hn));
            hp = hc; hc = hn;
        }
    } else {
        // ---------- general path: arbitrary 3x3 mask ----------
        float oob[3];
        #pragma unroll
        for (int i = 0; i < 3; ++i)
            oob[i] = MAXV + fminf(fminf(kb[i][0], kb[i][1]), kb[i][2]);

        // output y = min( h0(y-1), h1(y), h2(y+1) ), hi = biased hmin w/ mask row i
        float4 h0_prev, h1_cur;
        if (y0 == 0) {
            h0_prev = f4const(oob[0]);
        } else {
            h0_prev = hmin_bias(p + (size_t)(y0 - 1) * W, x4, kb[0][0], kb[0][1], kb[0][2]);
        }
        h1_cur = hmin_bias(p + (size_t)y0 * W, x4, kb[1][0], kb[1][1], kb[1][2]);

        for (int r = 0; r < STRIP; ++r) {
            const int y = y0 + r;
            float4 h2_next, h0_cur_next, h1_next;
            if (y + 1 < H) {
                const float* row = p + (size_t)(y + 1) * W;
                h2_next     = hmin_bias(row, x4, kb[2][0], kb[2][1], kb[2][2]);
                h0_cur_next = hmin_bias(row, x4, kb[0][0], kb[0][1], kb[0][2]);
                h1_next     = hmin_bias(row, x4, kb[1][0], kb[1][1], kb[1][2]);
            } else {
                h2_next     = f4const(oob[2]);
                h0_cur_next = f4const(oob[0]);
                h1_next     = f4const(oob[1]);
            }
            *reinterpret_cast<float4*>(q + (size_t)y * W + x4) =
                min3v(h0_prev, h1_cur, h2_next);
            h0_prev = h0_cur_next;
            h1_cur  = h1_next;
        }
    }
}

extern "C" void kernel_launch(void* const* d_in, const int* in_sizes, int n_in,
                              void* d_out, int out_size) {
    const float* x = (const float*)d_in[0];
    const float* k = (const float*)d_in[1];
    float* out = (float*)d_out;

    const int imgs = in_sizes[0] / (W * H);        // B*C = 64
    const int total_threads = imgs * NSTRIP * X4;  // 64 * 128 * 256 = 2,097,152
    const int block = 256;
    const int grid = total_threads / block;        // 8192

    erosion3x3_kernel<<<grid, block>>>(x, k, out);
}

// round 14
// speedup vs baseline: 1.0051x; 1.0051x over previous
#include <cuda_runtime.h>
#include <cstdint>

#define MAXV 10000.0f

namespace {
constexpr int W = 1024;
constexpr int H = 1024;
constexpr int X4 = W / 4;         // 256 float4 columns
constexpr int STRIP = 8;          // output rows per thread
constexpr int NSTRIP = H / STRIP; // 128
}

__device__ __forceinline__ float4 f4const(float v) {
    return make_float4(v, v, v, v);
}

__device__ __forceinline__ float4 min3v(float4 a, float4 b, float4 c) {
    float4 o;
    o.x = fminf(fminf(a.x, b.x), c.x);
    o.y = fminf(fminf(a.y, b.y), c.y);
    o.z = fminf(fminf(a.z, b.z), c.z);
    o.w = fminf(fminf(a.w, b.w), c.w);
    return o;
}

// Horizontal min over {x-1, x, x+1}, no kernel bias (all taps active).
// The scalar halo loads hit 128B lines already fetched by neighboring lanes'
// float4 loads -> L1/L2 hits, no extra DRAM traffic.
__device__ __forceinline__ float4 hmin_fast(const float* __restrict__ row, int x4) {
    const float4 v = *reinterpret_cast<const float4*>(row + x4);
    const float l = (x4 == 0) ? MAXV : row[x4 - 1];
    const float r = (x4 == W - 4) ? MAXV : row[x4 + 4];
    float4 h;
    h.x = fminf(fminf(l,   v.x), v.y);
    h.y = fminf(fminf(v.x, v.y), v.z);
    h.z = fminf(fminf(v.y, v.z), v.w);
    h.w = fminf(fminf(v.z, v.w), r);
    return h;
}

// Horizontal min with per-tap bias (bias = +MAXV where kernel tap == 0).
__device__ __forceinline__ float4 hmin_bias(const float* __restrict__ row, int x4,
                                            float b0, float b1, float b2) {
    const float4 v = *reinterpret_cast<const float4*>(row + x4);
    const float l = (x4 == 0) ? MAXV : row[x4 - 1];
    const float r = (x4 == W - 4) ? MAXV : row[x4 + 4];
    float4 h;
    h.x = fminf(fminf(l   + b0, v.x + b1), v.y + b2);
    h.y = fminf(fminf(v.x + b0, v.y + b1), v.z + b2);
    h.z = fminf(fminf(v.y + b0, v.z + b1), v.w + b2);
    h.w = fminf(fminf(v.z + b0, v.w + b1), r   + b2);
    return h;
}

__global__ void __launch_bounds__(256)
erosion3x3_kernel(const float* __restrict__ in,
                  const float* __restrict__ kern,
                  float* __restrict__ out) {
    const int t = blockIdx.x * blockDim.x + threadIdx.x;
    const int x4    = (t & (X4 - 1)) << 2;          // 0..1020 (16B aligned)
    const int strip = (t >> 8) & (NSTRIP - 1);      // 0..127
    const int img   = t >> 15;                      // image index (B*C)

    const size_t base = (size_t)img * (size_t)(W * H);
    const float* __restrict__ p = in  + base;
    float*       __restrict__ q = out + base;
    const int y0 = strip * STRIP;

    // Read 3x3 structuring element; bias = +MAXV where tap == 0
    // (reference: term = padded - neigh, neigh = -MAXV for inactive taps).
    float kb[3][3];
    bool allActive = true;
    #pragma unroll
    for (int i = 0; i < 3; ++i)
        #pragma unroll
        for (int j = 0; j < 3; ++j) {
            const float kv = kern[i * 3 + j];
            const bool act = (kv != 0.0f);
            kb[i][j] = act ? 0.0f : MAXV;
            allActive &= act;
        }

    if (allActive) {
        // ---------- fast path: plain 3x3 min filter, rolling vertical min ----------
        float4 hp = (y0 == 0) ? f4const(MAXV) : hmin_fast(p + (size_t)(y0 - 1) * W, x4);
        float4 hc = hmin_fast(p + (size_t)y0 * W, x4);
        #pragma unroll
        for (int r = 0; r < STRIP; ++r) {
            const int y = y0 + r;
            const float4 hn = (y + 1 < H) ? hmin_fast(p + (size_t)(y + 1) * W, x4)
                                          : f4const(MAXV);
            __stcs(reinterpret_cast<float4*>(q + (size_t)y * W + x4), min3v(hp, hc, hn));
            hp = hc; hc = hn;
        }
    } else {
        // ---------- general path: arbitrary 3x3 mask ----------
        float oob[3];
        #pragma unroll
        for (int i = 0; i < 3; ++i)
            oob[i] = MAXV + fminf(fminf(kb[i][0], kb[i][1]), kb[i][2]);

        // output y = min( h0(y-1), h1(y), h2(y+1) ), hi = biased hmin w/ mask row i
        float4 h0_prev, h1_cur;
        if (y0 == 0) {
            h0_prev = f4const(oob[0]);
        } else {
            h0_prev = hmin_bias(p + (size_t)(y0 - 1) * W, x4, kb[0][0], kb[0][1], kb[0][2]);
        }
        h1_cur = hmin_bias(p + (size_t)y0 * W, x4, kb[1][0], kb[1][1], kb[1][2]);

        for (int r = 0; r < STRIP; ++r) {
            const int y = y0 + r;
            float4 h2_next, h0_cur_next, h1_next;
            if (y + 1 < H) {
                const float* row = p + (size_t)(y + 1) * W;
                h2_next     = hmin_bias(row, x4, kb[2][0], kb[2][1], kb[2][2]);
                h0_cur_next = hmin_bias(row, x4, kb[0][0], kb[0][1], kb[0][2]);
                h1_next     = hmin_bias(row, x4, kb[1][0], kb[1][1], kb[1][2]);
            } else {
                h2_next     = f4const(oob[2]);
                h0_cur_next = f4const(oob[0]);
                h1_next     = f4const(oob[1]);
            }
            *reinterpret_cast<float4*>(q + (size_t)y * W + x4) =
                min3v(h0_prev, h1_cur, h2_next);
            h0_prev = h0_cur_next;
            h1_cur  = h1_next;
        }
    }
}

extern "C" void kernel_launch(void* const* d_in, const int* in_sizes, int n_in,
                              void* d_out, int out_size) {
    const float* x = (const float*)d_in[0];
    const float* k = (const float*)d_in[1];
    float* out = (float*)d_out;

    const int imgs = in_sizes[0] / (W * H);        // B*C = 64
    const int total_threads = imgs * NSTRIP * X4;  // 64 * 128 * 256 = 2,097,152
    const int block = 256;
    const int grid = total_threads / block;        // 8192

    erosion3x3_kernel<<<grid, block>>>(x, k, out);
}